// round 1
// baseline (speedup 1.0000x reference)
#include <cuda_runtime.h>
#include <cstdint>
#include <cstddef>

// ---------------- problem constants (fixed shapes) ----------------
#define N_PTS 524288
#define BB 2
#define FF 4
#define HH 64
#define WW 512
#define SS (BB*FF*HH*WW)        // 262144 voxels
#define EPSBN 1e-5f

// ---------------- static device scratch (no allocs allowed) ----------------
__device__ float g_counts[SS];
__device__ float g_vsum[SS*3];
__device__ int   g_lin[N_PTS];
__device__ float g_feats[(size_t)N_PTS*8];
__device__ float g_y1[(size_t)N_PTS*64];
__device__ float g_y2[(size_t)N_PTS*128];
__device__ float g_y3[(size_t)N_PTS*256];
__device__ int   g_voxmax[(size_t)SS*256];
__device__ float g_comp[(size_t)SS*64];
__device__ float g_stat[512];          // [0:256) sum, [256:512) sumsq
__device__ float g_scale[4*256];
__device__ float g_shift[4*256];

// ---------------- helpers ----------------
__device__ __forceinline__ int f2mono(float f){
    int i = __float_as_int(f);
    return i >= 0 ? i : (i ^ 0x7FFFFFFF);
}
__device__ __forceinline__ float mono2f(int m){
    return __int_as_float(m >= 0 ? m : (m ^ 0x7FFFFFFF));
}

// ---------------- init / zero ----------------
__global__ void init_k(){
    long stride = (long)gridDim.x * blockDim.x;
    for (long i = (long)blockIdx.x*blockDim.x + threadIdx.x; i < (long)SS*256; i += stride){
        g_voxmax[i] = 0x80000000;   // INT_MIN sentinel (== empty)
        if (i < SS)    g_counts[i] = 0.0f;
        if (i < SS*3)  g_vsum[i]   = 0.0f;
    }
}
__global__ void zstat_k(){ g_stat[threadIdx.x] = 0.0f; }

// ---------------- scatter: lin index, counts, coord sums ----------------
__global__ __launch_bounds__(256) void scatter_k(const float* __restrict__ pts,
                                                 const int* __restrict__ coors){
    int i = blockIdx.x*blockDim.x + threadIdx.x;
    if (i >= N_PTS) return;
    int c0 = coors[4*i+0], c1 = coors[4*i+1], c2 = coors[4*i+2], c3 = coors[4*i+3];
    int l = ((c0*FF + c1)*HH + c2)*WW + c3;
    g_lin[i] = l;
    float4 p = *(const float4*)&pts[4*i];
    atomicAdd(&g_counts[l], 1.0f);
    atomicAdd(&g_vsum[3*l+0], p.x);
    atomicAdd(&g_vsum[3*l+1], p.y);
    atomicAdd(&g_vsum[3*l+2], p.z);
}

// ---------------- feats (N x 8) + channel stats ----------------
__global__ __launch_bounds__(256) void feats_k(const float* __restrict__ pts){
    int i = blockIdx.x*blockDim.x + threadIdx.x;
    float f[8];
    float4 p = *(const float4*)&pts[4*i];
    int l = g_lin[i];
    float inv = 1.0f / fmaxf(g_counts[l], 1.0f);
    float mx = g_vsum[3*l+0]*inv, my = g_vsum[3*l+1]*inv, mz = g_vsum[3*l+2]*inv;
    f[0]=p.x; f[1]=p.y; f[2]=p.z; f[3]=p.w;
    f[4]=sqrtf(p.x*p.x + p.y*p.y + p.z*p.z);
    f[5]=p.x-mx; f[6]=p.y-my; f[7]=p.z-mz;
    *(float4*)&g_feats[(size_t)i*8]   = make_float4(f[0],f[1],f[2],f[3]);
    *(float4*)&g_feats[(size_t)i*8+4] = make_float4(f[4],f[5],f[6],f[7]);
    #pragma unroll
    for (int ch = 0; ch < 8; ch++){
        float s = f[ch], q = f[ch]*f[ch];
        #pragma unroll
        for (int o = 16; o; o >>= 1){
            s += __shfl_xor_sync(0xFFFFFFFFu, s, o);
            q += __shfl_xor_sync(0xFFFFFFFFu, q, o);
        }
        if ((threadIdx.x & 31) == 0){
            atomicAdd(&g_stat[ch], s);
            atomicAdd(&g_stat[256+ch], q);
        }
    }
}

// ---------------- BN params from stats ----------------
__global__ void bnparam_k(const float* __restrict__ gam, const float* __restrict__ bet,
                          int C, int layer){
    int c = threadIdx.x;
    if (c < C){
        float n = (float)N_PTS;
        float m = g_stat[c] / n;
        float v = g_stat[256+c] / n - m*m;
        float sc = gam[c] / sqrtf(v + EPSBN);
        g_scale[layer*256+c] = sc;
        g_shift[layer*256+c] = bet[c] - m*sc;
    }
}

// ---------------- column stats of y (N x C), C in {64,128,256} ----------------
__global__ __launch_bounds__(256) void stats_k(const float* __restrict__ y, int C){
    int tid = threadIdx.x;
    int rpb = 256 / C;
    int c  = tid % C;
    int rr = tid / C;
    float s = 0.0f, q = 0.0f;
    for (long row = (long)blockIdx.x*rpb + rr; row < N_PTS; row += (long)gridDim.x*rpb){
        float v = y[row*(long)C + c];
        s += v; q += v*v;
    }
    __shared__ float sm[256];
    sm[tid] = s; __syncthreads();
    if (tid < C){
        float t = 0.0f;
        for (int j = 0; j < rpb; j++) t += sm[tid + j*C];
        atomicAdd(&g_stat[tid], t);
    }
    __syncthreads();
    sm[tid] = q; __syncthreads();
    if (tid < C){
        float t = 0.0f;
        for (int j = 0; j < rpb; j++) t += sm[tid + j*C];
        atomicAdd(&g_stat[256+tid], t);
    }
}

// ---------------- layer 1: feats(8) -> y1(64), BN0 affine on load ----------------
__global__ __launch_bounds__(128) void gemm1_k(const float* __restrict__ W1){
    __shared__ float Ws[8][64];
    __shared__ float sc[8], sh[8];
    int tid = threadIdx.x;
    for (int i = tid; i < 512; i += 128) Ws[i>>6][i&63] = W1[i];
    if (tid < 8){ sc[tid] = g_scale[tid]; sh[tid] = g_shift[tid]; }
    __syncthreads();
    int row = blockIdx.x*128 + tid;
    float4 fa = *(const float4*)&g_feats[(size_t)row*8];
    float4 fb = *(const float4*)&g_feats[(size_t)row*8+4];
    float f[8] = {fa.x,fa.y,fa.z,fa.w,fb.x,fb.y,fb.z,fb.w};
    #pragma unroll
    for (int k = 0; k < 8; k++) f[k] = f[k]*sc[k] + sh[k];
    #pragma unroll
    for (int c4 = 0; c4 < 16; c4++){
        float4 acc = make_float4(0,0,0,0);
        #pragma unroll
        for (int k = 0; k < 8; k++){
            float4 w = *(const float4*)&Ws[k][c4*4];
            acc.x += f[k]*w.x; acc.y += f[k]*w.y;
            acc.z += f[k]*w.z; acc.w += f[k]*w.w;
        }
        *(float4*)&g_y1[(size_t)row*64 + c4*4] = acc;
    }
}

// ---------------- big GEMM: A(NxK, affine+relu on load) @ W(KxCout) ----------------
// EPI 0: store Y.  EPI 1: += bias then scatter atomicMax into g_voxmax (via g_lin).
template<int K, bool RELU_IN, int EPI>
__global__ __launch_bounds__(256) void gemm_big_k(const float* __restrict__ A,
                                                  const float* __restrict__ W,
                                                  float* __restrict__ Y,
                                                  int Cout,
                                                  const float* __restrict__ bias,
                                                  int layer){
    __shared__ float As[16][132];
    __shared__ float Bs[16][128];
    __shared__ float ssc[K], ssh[K];
    __shared__ int   slin[128];
    int tid = threadIdx.x;
    int row0 = blockIdx.x*128, col0 = blockIdx.y*128;
    for (int i = tid; i < K; i += 256){ ssc[i] = g_scale[layer*256+i]; ssh[i] = g_shift[layer*256+i]; }
    if (EPI == 1){ if (tid < 128) slin[tid] = g_lin[row0 + tid]; }
    __syncthreads();

    float acc[8][8];
    #pragma unroll
    for (int i = 0; i < 8; i++)
        #pragma unroll
        for (int j = 0; j < 8; j++) acc[i][j] = 0.0f;

    int tr = tid >> 4, tc = tid & 15;

    for (int k0 = 0; k0 < K; k0 += 16){
        #pragma unroll
        for (int i = 0; i < 8; i++){
            int idx = tid + i*256;
            int k = idx & 15, r = idx >> 4;
            float v = A[(size_t)(row0+r)*K + k0 + k];
            v = v*ssc[k0+k] + ssh[k0+k];
            if (RELU_IN) v = fmaxf(v, 0.0f);
            As[k][r] = v;
        }
        #pragma unroll
        for (int i = 0; i < 8; i++){
            int idx = tid + i*256;
            int c = idx & 127, k = idx >> 7;
            Bs[k][c] = W[(size_t)(k0+k)*Cout + col0 + c];
        }
        __syncthreads();
        #pragma unroll
        for (int kk = 0; kk < 16; kk++){
            float4 a0 = *(const float4*)&As[kk][tr*8];
            float4 a1 = *(const float4*)&As[kk][tr*8+4];
            float4 b0 = *(const float4*)&Bs[kk][tc*8];
            float4 b1 = *(const float4*)&Bs[kk][tc*8+4];
            float av[8] = {a0.x,a0.y,a0.z,a0.w,a1.x,a1.y,a1.z,a1.w};
            float bv[8] = {b0.x,b0.y,b0.z,b0.w,b1.x,b1.y,b1.z,b1.w};
            #pragma unroll
            for (int i = 0; i < 8; i++)
                #pragma unroll
                for (int j = 0; j < 8; j++)
                    acc[i][j] += av[i]*bv[j];
        }
        __syncthreads();
    }

    if (EPI == 0){
        #pragma unroll
        for (int i = 0; i < 8; i++){
            size_t base = (size_t)(row0 + tr*8 + i)*Cout + col0 + tc*8;
            *(float4*)&Y[base]   = make_float4(acc[i][0],acc[i][1],acc[i][2],acc[i][3]);
            *(float4*)&Y[base+4] = make_float4(acc[i][4],acc[i][5],acc[i][6],acc[i][7]);
        }
    } else {
        float bb[8];
        #pragma unroll
        for (int j = 0; j < 8; j++) bb[j] = bias[col0 + tc*8 + j];
        #pragma unroll
        for (int i = 0; i < 8; i++){
            int l = slin[tr*8 + i];
            int base = l*256 + col0 + tc*8;
            #pragma unroll
            for (int j = 0; j < 8; j++){
                atomicMax(&g_voxmax[base + j], f2mono(acc[i][j] + bb[j]));
            }
        }
    }
}

// ---------------- voxel GEMM: masked voxmax(Sx256) @ Wc(256x64) + bc, relu, mask ----------------
__global__ __launch_bounds__(256) void gemm_comp_k(const float* __restrict__ Wc,
                                                   const float* __restrict__ bc){
    __shared__ float As[16][132];
    __shared__ float Bs[16][64];
    __shared__ float scount[128];
    __shared__ float sbc[64];
    int tid = threadIdx.x;
    int row0 = blockIdx.x*128;
    if (tid < 128) scount[tid] = g_counts[row0 + tid];
    if (tid < 64)  sbc[tid] = bc[tid];
    __syncthreads();

    float acc[8][4];
    #pragma unroll
    for (int i = 0; i < 8; i++)
        #pragma unroll
        for (int j = 0; j < 4; j++) acc[i][j] = 0.0f;

    int tr = tid >> 4, tc = tid & 15;

    for (int k0 = 0; k0 < 256; k0 += 16){
        #pragma unroll
        for (int i = 0; i < 8; i++){
            int idx = tid + i*256;
            int k = idx & 15, r = idx >> 4;
            int m = g_voxmax[(size_t)(row0+r)*256 + k0 + k];
            As[k][r] = (m == (int)0x80000000) ? 0.0f : mono2f(m);
        }
        #pragma unroll
        for (int i = 0; i < 4; i++){
            int idx = tid + i*256;
            int c = idx & 63, k = idx >> 6;
            Bs[k][c] = Wc[(size_t)(k0+k)*64 + c];
        }
        __syncthreads();
        #pragma unroll
        for (int kk = 0; kk < 16; kk++){
            float4 a0 = *(const float4*)&As[kk][tr*8];
            float4 a1 = *(const float4*)&As[kk][tr*8+4];
            float4 b0 = *(const float4*)&Bs[kk][tc*4];
            float av[8] = {a0.x,a0.y,a0.z,a0.w,a1.x,a1.y,a1.z,a1.w};
            float bv[4] = {b0.x,b0.y,b0.z,b0.w};
            #pragma unroll
            for (int i = 0; i < 8; i++)
                #pragma unroll
                for (int j = 0; j < 4; j++)
                    acc[i][j] += av[i]*bv[j];
        }
        __syncthreads();
    }

    #pragma unroll
    for (int i = 0; i < 8; i++){
        int r = tr*8 + i;
        float mask = (scount[r] > 0.0f) ? 1.0f : 0.0f;
        float4 o;
        o.x = fmaxf(acc[i][0] + sbc[tc*4+0], 0.0f) * mask;
        o.y = fmaxf(acc[i][1] + sbc[tc*4+1], 0.0f) * mask;
        o.z = fmaxf(acc[i][2] + sbc[tc*4+2], 0.0f) * mask;
        o.w = fmaxf(acc[i][3] + sbc[tc*4+3], 0.0f) * mask;
        *(float4*)&g_comp[(size_t)(row0 + r)*64 + tc*4] = o;
    }
}

// ---------------- residual assembly: out (B, 192, H, W) ----------------
__global__ __launch_bounds__(256) void residual_k(float* __restrict__ out){
    int idx = blockIdx.x*blockDim.x + threadIdx.x;
    const int TOT = BB*192*HH*WW;
    if (idx >= TOT) return;
    int w  = idx % WW;
    int h  = (idx / WW) % HH;
    int ch = (idx / (WW*HH)) % 192;
    int b  = idx / (WW*HH*192);
    int f = ch >> 6, j = ch & 63;
    int vl = ((b*FF + (FF-1))*HH + h)*WW + w;
    int vf = ((b*FF + f)*HH + h)*WW + w;
    out[idx] = g_comp[(size_t)vl*64 + j] - g_comp[(size_t)vf*64 + j];
}

// ---------------- host launcher ----------------
extern "C" void kernel_launch(void* const* d_in, const int* in_sizes, int n_in,
                              void* d_out, int out_size){
    const float* pts   = (const float*)d_in[0];
    const int*   coors = (const int*)  d_in[1];
    const float* pre_g = (const float*)d_in[2];
    const float* pre_b = (const float*)d_in[3];
    const float* W1    = (const float*)d_in[4];
    const float* g1    = (const float*)d_in[5];
    const float* b1    = (const float*)d_in[6];
    const float* W2    = (const float*)d_in[7];
    const float* g2    = (const float*)d_in[8];
    const float* b2    = (const float*)d_in[9];
    const float* W3    = (const float*)d_in[10];
    const float* g3    = (const float*)d_in[11];
    const float* b3    = (const float*)d_in[12];
    const float* W4    = (const float*)d_in[13];
    const float* b4    = (const float*)d_in[14];
    const float* Wc    = (const float*)d_in[15];
    const float* bc    = (const float*)d_in[16];
    float* out = (float*)d_out;

    void *p_feats, *p_y1, *p_y2, *p_y3;
    cudaGetSymbolAddress(&p_feats, g_feats);
    cudaGetSymbolAddress(&p_y1, g_y1);
    cudaGetSymbolAddress(&p_y2, g_y2);
    cudaGetSymbolAddress(&p_y3, g_y3);
    float* y1 = (float*)p_y1;
    float* y2 = (float*)p_y2;
    float* y3 = (float*)p_y3;

    // 0. init sentinels / accumulators
    init_k<<<4096, 256>>>();
    zstat_k<<<1, 512>>>();

    // 1. voxel scatter (counts, coord sums, lin)
    scatter_k<<<N_PTS/256, 256>>>(pts, coors);

    // 2. feats + pre-norm stats
    feats_k<<<N_PTS/256, 256>>>(pts);
    bnparam_k<<<1, 256>>>(pre_g, pre_b, 8, 0);

    // 3. layer 1: 8 -> 64
    gemm1_k<<<N_PTS/128, 128>>>(W1);
    zstat_k<<<1, 512>>>();
    stats_k<<<2048, 256>>>(y1, 64);
    bnparam_k<<<1, 256>>>(g1, b1, 64, 1);

    // 4. layer 2: 64 -> 128
    gemm_big_k<64, true, 0><<<dim3(N_PTS/128, 1), 256>>>(y1, W2, y2, 128, nullptr, 1);
    zstat_k<<<1, 512>>>();
    stats_k<<<2048, 256>>>(y2, 128);
    bnparam_k<<<1, 256>>>(g2, b2, 128, 2);

    // 5. layer 3: 128 -> 256
    gemm_big_k<128, true, 0><<<dim3(N_PTS/128, 2), 256>>>(y2, W3, y3, 256, nullptr, 2);
    zstat_k<<<1, 512>>>();
    stats_k<<<2048, 256>>>(y3, 256);
    bnparam_k<<<1, 256>>>(g3, b3, 256, 3);

    // 6. layer 4: 256 -> 256 (+b4) fused with voxel scatter-max
    gemm_big_k<256, true, 1><<<dim3(N_PTS/128, 2), 256>>>(y3, W4, nullptr, 256, b4, 3);

    // 7. voxel compress: 256 -> 64, relu, empty-mask
    gemm_comp_k<<<SS/128, 256>>>(Wc, bc);

    // 8. frame residual output
    const int TOT = BB*192*HH*WW;
    residual_k<<<(TOT + 255)/256, 256>>>(out);

    (void)in_sizes; (void)n_in; (void)out_size;
}

// round 4
// speedup vs baseline: 1.9790x; 1.9790x over previous
#include <cuda_runtime.h>
#include <cstdint>
#include <cstddef>

// ---------------- problem constants ----------------
#define N_PTS 524288
#define BB 2
#define FF 4
#define HH 64
#define WW 512
#define SS (BB*FF*HH*WW)        // 262144 voxels
#define EPSBN 1e-5f

// ---------------- static device scratch ----------------
__device__ int   g_cnt[SS];
__device__ int   g_off[SS];
__device__ int   g_cursor[SS];
__device__ int   g_bsum[256];
__device__ int   g_boff[256];
__device__ int   g_csr[N_PTS];
__device__ float g_vsum[SS*3];
__device__ int   g_lin[N_PTS];
__device__ float g_feats[(size_t)N_PTS*8];
__device__ float g_y1[(size_t)N_PTS*64];
__device__ float g_y2[(size_t)N_PTS*128];
__device__ float g_y3[(size_t)N_PTS*256];
__device__ float g_y4[(size_t)N_PTS*256];
__device__ float g_comp[(size_t)SS*64];
__device__ float g_stat[512];          // [0:256) sum, [256:512) sumsq
__device__ float g_scale[4*256];
__device__ float g_shift[4*256];
__device__ float g_wt2[128*64];        // W2^T [n][k] tf32-rounded
__device__ float g_wt3[256*128];
__device__ float g_wt4[256*256];
__device__ float g_wtc[64*256];

// ---------------- helpers ----------------
__device__ __forceinline__ float tf32r(float x){
    uint32_t o;
    asm("cvt.rna.tf32.f32 %0, %1;" : "=r"(o) : "r"(__float_as_uint(x)));
    return __uint_as_float(o);
}
__device__ __forceinline__ void mma8(float* c, const uint32_t* a, uint32_t b0, uint32_t b1){
    asm volatile(
        "mma.sync.aligned.m16n8k8.row.col.f32.tf32.tf32.f32 "
        "{%0,%1,%2,%3}, {%4,%5,%6,%7}, {%8,%9}, {%0,%1,%2,%3};"
        : "+f"(c[0]), "+f"(c[1]), "+f"(c[2]), "+f"(c[3])
        : "r"(a[0]), "r"(a[1]), "r"(a[2]), "r"(a[3]), "r"(b0), "r"(b1));
}

// ---------------- small kernels ----------------
__global__ void init_k(){
    long stride = (long)gridDim.x * blockDim.x;
    for (long i = (long)blockIdx.x*blockDim.x + threadIdx.x; i < (long)SS*3; i += stride){
        g_vsum[i] = 0.0f;
        if (i < SS) g_cnt[i] = 0;
    }
}
__global__ void zstat_k(){ g_stat[threadIdx.x] = 0.0f; }

__global__ __launch_bounds__(256) void scatter_k(const float* __restrict__ pts,
                                                 const int* __restrict__ coors){
    int i = blockIdx.x*blockDim.x + threadIdx.x;
    if (i >= N_PTS) return;
    int c0 = coors[4*i+0], c1 = coors[4*i+1], c2 = coors[4*i+2], c3 = coors[4*i+3];
    int l = ((c0*FF + c1)*HH + c2)*WW + c3;
    g_lin[i] = l;
    float4 p = *(const float4*)&pts[4*i];
    atomicAdd(&g_cnt[l], 1);
    atomicAdd(&g_vsum[3*l+0], p.x);
    atomicAdd(&g_vsum[3*l+1], p.y);
    atomicAdd(&g_vsum[3*l+2], p.z);
}

// prefix scan of counts -> CSR offsets
__global__ __launch_bounds__(1024) void scan1_k(){
    __shared__ int s[1024];
    int t = threadIdx.x, g = blockIdx.x*1024 + t;
    int v = g_cnt[g]; s[t] = v; __syncthreads();
    #pragma unroll
    for (int d = 1; d < 1024; d <<= 1){
        int x = (t >= d) ? s[t-d] : 0; __syncthreads();
        s[t] += x; __syncthreads();
    }
    g_off[g] = s[t] - v;
    if (t == 1023) g_bsum[blockIdx.x] = s[t];
}
__global__ void scan2_k(){
    __shared__ int s[256];
    int t = threadIdx.x;
    int v = g_bsum[t]; s[t] = v; __syncthreads();
    #pragma unroll
    for (int d = 1; d < 256; d <<= 1){
        int x = (t >= d) ? s[t-d] : 0; __syncthreads();
        s[t] += x; __syncthreads();
    }
    g_boff[t] = s[t] - v;
}
__global__ __launch_bounds__(1024) void scan3_k(){
    int g = blockIdx.x*1024 + threadIdx.x;
    int o = g_off[g] + g_boff[blockIdx.x];
    g_off[g] = o; g_cursor[g] = o;
}
__global__ __launch_bounds__(256) void csrfill_k(){
    int i = blockIdx.x*256 + threadIdx.x;
    int l = g_lin[i];
    int slot = atomicAdd(&g_cursor[l], 1);
    g_csr[slot] = i;
}

// feats (N x 8) + block-reduced channel stats
__global__ __launch_bounds__(256) void feats_k(const float* __restrict__ pts){
    __shared__ float st[16];
    int tid = threadIdx.x;
    if (tid < 16) st[tid] = 0.0f;
    __syncthreads();
    int i = blockIdx.x*blockDim.x + tid;
    float4 p = *(const float4*)&pts[4*i];
    int l = g_lin[i];
    float inv = 1.0f / fmaxf((float)g_cnt[l], 1.0f);
    float mx = g_vsum[3*l+0]*inv, my = g_vsum[3*l+1]*inv, mz = g_vsum[3*l+2]*inv;
    float f[8];
    f[0]=p.x; f[1]=p.y; f[2]=p.z; f[3]=p.w;
    f[4]=sqrtf(p.x*p.x + p.y*p.y + p.z*p.z);
    f[5]=p.x-mx; f[6]=p.y-my; f[7]=p.z-mz;
    *(float4*)&g_feats[(size_t)i*8]   = make_float4(f[0],f[1],f[2],f[3]);
    *(float4*)&g_feats[(size_t)i*8+4] = make_float4(f[4],f[5],f[6],f[7]);
    #pragma unroll
    for (int ch = 0; ch < 8; ch++){
        float s = f[ch], q = f[ch]*f[ch];
        #pragma unroll
        for (int o = 16; o; o >>= 1){
            s += __shfl_xor_sync(0xFFFFFFFFu, s, o);
            q += __shfl_xor_sync(0xFFFFFFFFu, q, o);
        }
        if ((tid & 31) == 0){
            atomicAdd(&st[ch], s);
            atomicAdd(&st[8+ch], q);
        }
    }
    __syncthreads();
    if (tid < 8)              atomicAdd(&g_stat[tid], st[tid]);
    else if (tid < 16)        atomicAdd(&g_stat[256 + tid - 8], st[tid]);
}

__global__ void bnparam_k(const float* __restrict__ gam, const float* __restrict__ bet,
                          int C, int layer){
    int c = threadIdx.x;
    if (c < C){
        float n = (float)N_PTS;
        float m = g_stat[c] / n;
        float v = g_stat[256+c] / n - m*m;
        float sc = gam[c] / sqrtf(v + EPSBN);
        g_scale[layer*256+c] = sc;
        g_shift[layer*256+c] = bet[c] - m*sc;
    }
}

__global__ __launch_bounds__(256) void stats_k(const float* __restrict__ y, int C){
    int tid = threadIdx.x;
    int rpb = 256 / C;
    int c  = tid % C;
    int rr = tid / C;
    float s = 0.0f, q = 0.0f;
    for (long row = (long)blockIdx.x*rpb + rr; row < N_PTS; row += (long)gridDim.x*rpb){
        float v = y[row*(long)C + c];
        s += v; q += v*v;
    }
    __shared__ float sm[256];
    sm[tid] = s; __syncthreads();
    if (tid < C){
        float t = 0.0f;
        for (int j = 0; j < rpb; j++) t += sm[tid + j*C];
        atomicAdd(&g_stat[tid], t);
    }
    __syncthreads();
    sm[tid] = q; __syncthreads();
    if (tid < C){
        float t = 0.0f;
        for (int j = 0; j < rpb; j++) t += sm[tid + j*C];
        atomicAdd(&g_stat[256+tid], t);
    }
}

// layer 1: feats(8) -> y1(64), BN0 affine on load (SIMT)
__global__ __launch_bounds__(128) void gemm1_k(const float* __restrict__ W1){
    __shared__ float Ws[8][64];
    __shared__ float sc[8], sh[8];
    int tid = threadIdx.x;
    for (int i = tid; i < 512; i += 128) Ws[i>>6][i&63] = W1[i];
    if (tid < 8){ sc[tid] = g_scale[tid]; sh[tid] = g_shift[tid]; }
    __syncthreads();
    int row = blockIdx.x*128 + tid;
    float4 fa = *(const float4*)&g_feats[(size_t)row*8];
    float4 fb = *(const float4*)&g_feats[(size_t)row*8+4];
    float f[8] = {fa.x,fa.y,fa.z,fa.w,fb.x,fb.y,fb.z,fb.w};
    #pragma unroll
    for (int k = 0; k < 8; k++) f[k] = f[k]*sc[k] + sh[k];
    #pragma unroll
    for (int c4 = 0; c4 < 16; c4++){
        float4 acc = make_float4(0,0,0,0);
        #pragma unroll
        for (int k = 0; k < 8; k++){
            float4 w = *(const float4*)&Ws[k][c4*4];
            acc.x += f[k]*w.x; acc.y += f[k]*w.y;
            acc.z += f[k]*w.z; acc.w += f[k]*w.w;
        }
        *(float4*)&g_y1[(size_t)row*64 + c4*4] = acc;
    }
}

// transpose W [K][C] -> Wt [C][K], tf32-round
__global__ __launch_bounds__(256) void tr_k(const float* __restrict__ W,
                                            float* __restrict__ Wt, int Kd, int Cd){
    int i = blockIdx.x*256 + threadIdx.x;
    if (i >= Kd*Cd) return;
    int n = i / Kd, k = i % Kd;
    Wt[i] = tf32r(W[k*Cd + n]);
}

// ---------------- mma.sync tf32 GEMM ----------------
// Y[N x COUT] = relu(A*scale+shift) @ Bt^T + (bias)
// A row-major [N][K] fp32, Bt [COUT][K] tf32-rounded.
// Block tile 128x128, BK=32, 8 warps (4 m x 2 n), warp tile 32x64.
template<int K, int COUT, bool ADD_BIAS>
__global__ __launch_bounds__(256) void mm_k(const float* __restrict__ A,
                                            const float* __restrict__ Bt,
                                            float* __restrict__ Y,
                                            const float* __restrict__ bias,
                                            int layer){
    __shared__ float As[128][36];
    __shared__ float Bs[128][36];
    constexpr int NIT = K/32;

    int tid = threadIdx.x, wid = tid >> 5, lane = tid & 31;
    int row0 = blockIdx.x*128, col0 = blockIdx.y*128;
    int m_base = (wid & 3)*32, n_base = (wid >> 2)*64;
    int gr = lane >> 2, q = lane & 3;

    int lr = tid >> 1;                 // 0..127 (row / n)
    int lk = (tid & 1)*16;             // k-offset within BK (float units)

    float acc[2][8][4];
    #pragma unroll
    for (int i = 0; i < 2; i++)
        #pragma unroll
        for (int j = 0; j < 8; j++)
            #pragma unroll
            for (int c = 0; c < 4; c++) acc[i][j][c] = 0.0f;

    const float* scp = &g_scale[layer*256];
    const float* shp = &g_shift[layer*256];

    float4 ar[4], br[4];
    // prefetch iter 0
    {
        const float* Ap = &A[(size_t)(row0 + lr)*K + lk];
        const float* Bp = &Bt[(size_t)(col0 + lr)*K + lk];
        #pragma unroll
        for (int j = 0; j < 4; j++){ ar[j] = *(const float4*)&Ap[j*4]; br[j] = *(const float4*)&Bp[j*4]; }
    }
    // transform + store iter 0
    #pragma unroll
    for (int j = 0; j < 4; j++){
        float4 sc4 = *(const float4*)&scp[lk + j*4];
        float4 sh4 = *(const float4*)&shp[lk + j*4];
        float4 v = ar[j];
        v.x = tf32r(fmaxf(v.x*sc4.x + sh4.x, 0.0f));
        v.y = tf32r(fmaxf(v.y*sc4.y + sh4.y, 0.0f));
        v.z = tf32r(fmaxf(v.z*sc4.z + sh4.z, 0.0f));
        v.w = tf32r(fmaxf(v.w*sc4.w + sh4.w, 0.0f));
        *(float4*)&As[lr][lk + j*4] = v;
        *(float4*)&Bs[lr][lk + j*4] = br[j];
    }
    __syncthreads();

    for (int it = 0; it < NIT; it++){
        int k0n = (it+1)*32;
        if (it+1 < NIT){
            const float* Ap = &A[(size_t)(row0 + lr)*K + k0n + lk];
            const float* Bp = &Bt[(size_t)(col0 + lr)*K + k0n + lk];
            #pragma unroll
            for (int j = 0; j < 4; j++){ ar[j] = *(const float4*)&Ap[j*4]; br[j] = *(const float4*)&Bp[j*4]; }
        }
        #pragma unroll
        for (int kk = 0; kk < 4; kk++){
            int k = kk*8;
            uint32_t a[2][4];
            #pragma unroll
            for (int i = 0; i < 2; i++){
                int m = m_base + i*16 + gr;
                a[i][0] = __float_as_uint(As[m][k + q]);
                a[i][1] = __float_as_uint(As[m+8][k + q]);
                a[i][2] = __float_as_uint(As[m][k + 4 + q]);
                a[i][3] = __float_as_uint(As[m+8][k + 4 + q]);
            }
            #pragma unroll
            for (int j = 0; j < 8; j++){
                int n = n_base + j*8 + gr;
                uint32_t b0 = __float_as_uint(Bs[n][k + q]);
                uint32_t b1 = __float_as_uint(Bs[n][k + 4 + q]);
                mma8(acc[0][j], a[0], b0, b1);
                mma8(acc[1][j], a[1], b0, b1);
            }
        }
        if (it+1 < NIT){
            __syncthreads();
            #pragma unroll
            for (int j = 0; j < 4; j++){
                float4 sc4 = *(const float4*)&scp[k0n + lk + j*4];
                float4 sh4 = *(const float4*)&shp[k0n + lk + j*4];
                float4 v = ar[j];
                v.x = tf32r(fmaxf(v.x*sc4.x + sh4.x, 0.0f));
                v.y = tf32r(fmaxf(v.y*sc4.y + sh4.y, 0.0f));
                v.z = tf32r(fmaxf(v.z*sc4.z + sh4.z, 0.0f));
                v.w = tf32r(fmaxf(v.w*sc4.w + sh4.w, 0.0f));
                *(float4*)&As[lr][lk + j*4] = v;
                *(float4*)&Bs[lr][lk + j*4] = br[j];
            }
            __syncthreads();
        }
    }

    // epilogue: direct stores (float2 per fragment pair)
    #pragma unroll
    for (int i = 0; i < 2; i++){
        #pragma unroll
        for (int j = 0; j < 8; j++){
            int col = col0 + n_base + j*8 + 2*q;
            int r0 = row0 + m_base + i*16 + gr;
            float2 lo = make_float2(acc[i][j][0], acc[i][j][1]);
            float2 hi = make_float2(acc[i][j][2], acc[i][j][3]);
            if (ADD_BIAS){
                float bx = bias[col], by = bias[col+1];
                lo.x += bx; lo.y += by; hi.x += bx; hi.y += by;
            }
            *(float2*)&Y[(size_t)r0*COUT + col]     = lo;
            *(float2*)&Y[(size_t)(r0+8)*COUT + col] = hi;
        }
    }
}

// ---------------- voxel compress: CSR gather-max + tf32 mma 256->64 ----------------
// Block tile 128(vox) x 64, BK=32, 8 warps (4 m x 2 n), warp tile 32x32.
__global__ __launch_bounds__(256) void comp_k(const float* __restrict__ bc){
    __shared__ float As[128][36];
    __shared__ float Bs[64][36];
    __shared__ int scnt[128], soff[128];

    int tid = threadIdx.x, wid = tid >> 5, lane = tid & 31;
    int row0 = blockIdx.x*128;
    int m_base = (wid & 3)*32, n_base = (wid >> 2)*32;
    int gr = lane >> 2, q = lane & 3;

    if (tid < 128){ scnt[tid] = g_cnt[row0+tid]; soff[tid] = g_off[row0+tid]; }
    __syncthreads();

    float acc[2][4][4];
    #pragma unroll
    for (int i = 0; i < 2; i++)
        #pragma unroll
        for (int j = 0; j < 4; j++)
            #pragma unroll
            for (int c = 0; c < 4; c++) acc[i][j][c] = 0.0f;

    int v = tid >> 1, half = tid & 1;
    int cnt = scnt[v], off0 = soff[v];

    for (int it = 0; it < 8; it++){
        int k0 = it*32;
        // B: 64 x 32 from g_wtc
        #pragma unroll
        for (int i = 0; i < 2; i++){
            int idx = i*256 + tid;
            int n = idx >> 3, kq = idx & 7;
            *(float4*)&Bs[n][kq*4] = *(const float4*)&g_wtc[n*256 + k0 + kq*4];
        }
        // A: gather-max 16 cols per thread
        {
            int kbase = k0 + half*16;
            float4 m4[4];
            if (cnt == 0){
                #pragma unroll
                for (int t = 0; t < 4; t++) m4[t] = make_float4(0,0,0,0);
            } else {
                const float* src = &g_y4[(size_t)g_csr[off0]*256 + kbase];
                #pragma unroll
                for (int t = 0; t < 4; t++) m4[t] = *(const float4*)&src[t*4];
                for (int jj = 1; jj < cnt; jj++){
                    const float* sj = &g_y4[(size_t)g_csr[off0+jj]*256 + kbase];
                    #pragma unroll
                    for (int t = 0; t < 4; t++){
                        float4 w = *(const float4*)&sj[t*4];
                        m4[t].x = fmaxf(m4[t].x, w.x); m4[t].y = fmaxf(m4[t].y, w.y);
                        m4[t].z = fmaxf(m4[t].z, w.z); m4[t].w = fmaxf(m4[t].w, w.w);
                    }
                }
            }
            #pragma unroll
            for (int t = 0; t < 4; t++){
                m4[t].x = tf32r(m4[t].x); m4[t].y = tf32r(m4[t].y);
                m4[t].z = tf32r(m4[t].z); m4[t].w = tf32r(m4[t].w);
                *(float4*)&As[v][half*16 + t*4] = m4[t];
            }
        }
        __syncthreads();
        #pragma unroll
        for (int kk = 0; kk < 4; kk++){
            int k = kk*8;
            uint32_t a[2][4];
            #pragma unroll
            for (int i = 0; i < 2; i++){
                int m = m_base + i*16 + gr;
                a[i][0] = __float_as_uint(As[m][k + q]);
                a[i][1] = __float_as_uint(As[m+8][k + q]);
                a[i][2] = __float_as_uint(As[m][k + 4 + q]);
                a[i][3] = __float_as_uint(As[m+8][k + 4 + q]);
            }
            #pragma unroll
            for (int j = 0; j < 4; j++){
                int n = n_base + j*8 + gr;
                uint32_t b0 = __float_as_uint(Bs[n][k + q]);
                uint32_t b1 = __float_as_uint(Bs[n][k + 4 + q]);
                mma8(acc[0][j], a[0], b0, b1);
                mma8(acc[1][j], a[1], b0, b1);
            }
        }
        __syncthreads();
    }

    #pragma unroll
    for (int i = 0; i < 2; i++){
        #pragma unroll
        for (int j = 0; j < 4; j++){
            int col = n_base + j*8 + 2*q;
            int r0 = m_base + i*16 + gr;
            float m0 = (scnt[r0]   > 0) ? 1.0f : 0.0f;
            float m1 = (scnt[r0+8] > 0) ? 1.0f : 0.0f;
            float bx = bc[col], by = bc[col+1];
            float2 lo, hi;
            lo.x = fmaxf(acc[i][j][0] + bx, 0.0f)*m0;
            lo.y = fmaxf(acc[i][j][1] + by, 0.0f)*m0;
            hi.x = fmaxf(acc[i][j][2] + bx, 0.0f)*m1;
            hi.y = fmaxf(acc[i][j][3] + by, 0.0f)*m1;
            *(float2*)&g_comp[(size_t)(row0 + r0)*64 + col]     = lo;
            *(float2*)&g_comp[(size_t)(row0 + r0 + 8)*64 + col] = hi;
        }
    }
}

// ---------------- residual assembly: out (B, 192, H, W) ----------------
__global__ __launch_bounds__(256) void residual_k(float* __restrict__ out){
    int idx = blockIdx.x*blockDim.x + threadIdx.x;
    const int TOT = BB*192*HH*WW;
    if (idx >= TOT) return;
    int w  = idx % WW;
    int h  = (idx / WW) % HH;
    int ch = (idx / (WW*HH)) % 192;
    int b  = idx / (WW*HH*192);
    int f = ch >> 6, j = ch & 63;
    int vl = ((b*FF + (FF-1))*HH + h)*WW + w;
    int vf = ((b*FF + f)*HH + h)*WW + w;
    out[idx] = g_comp[(size_t)vl*64 + j] - g_comp[(size_t)vf*64 + j];
}

// ---------------- host launcher ----------------
extern "C" void kernel_launch(void* const* d_in, const int* in_sizes, int n_in,
                              void* d_out, int out_size){
    const float* pts   = (const float*)d_in[0];
    const int*   coors = (const int*)  d_in[1];
    const float* pre_g = (const float*)d_in[2];
    const float* pre_b = (const float*)d_in[3];
    const float* W1    = (const float*)d_in[4];
    const float* g1    = (const float*)d_in[5];
    const float* b1    = (const float*)d_in[6];
    const float* W2    = (const float*)d_in[7];
    const float* g2    = (const float*)d_in[8];
    const float* b2    = (const float*)d_in[9];
    const float* W3    = (const float*)d_in[10];
    const float* g3    = (const float*)d_in[11];
    const float* b3    = (const float*)d_in[12];
    const float* W4    = (const float*)d_in[13];
    const float* b4    = (const float*)d_in[14];
    const float* Wc    = (const float*)d_in[15];
    const float* bc    = (const float*)d_in[16];
    float* out = (float*)d_out;

    void *py1, *py2, *py3, *py4, *pwt2, *pwt3, *pwt4, *pwtc;
    cudaGetSymbolAddress(&py1, g_y1);
    cudaGetSymbolAddress(&py2, g_y2);
    cudaGetSymbolAddress(&py3, g_y3);
    cudaGetSymbolAddress(&py4, g_y4);
    cudaGetSymbolAddress(&pwt2, g_wt2);
    cudaGetSymbolAddress(&pwt3, g_wt3);
    cudaGetSymbolAddress(&pwt4, g_wt4);
    cudaGetSymbolAddress(&pwtc, g_wtc);

    // init + weight transposes
    init_k<<<1024, 256>>>();
    zstat_k<<<1, 512>>>();
    tr_k<<<(128*64 + 255)/256, 256>>>(W2, (float*)pwt2, 64, 128);
    tr_k<<<(256*128 + 255)/256, 256>>>(W3, (float*)pwt3, 128, 256);
    tr_k<<<(256*256 + 255)/256, 256>>>(W4, (float*)pwt4, 256, 256);
    tr_k<<<(64*256 + 255)/256, 256>>>(Wc, (float*)pwtc, 256, 64);

    // voxel scatter + CSR build
    scatter_k<<<N_PTS/256, 256>>>(pts, coors);
    scan1_k<<<SS/1024, 1024>>>();
    scan2_k<<<1, 256>>>();
    scan3_k<<<SS/1024, 1024>>>();
    csrfill_k<<<N_PTS/256, 256>>>();

    // feats + pre-norm
    feats_k<<<N_PTS/256, 256>>>(pts);
    bnparam_k<<<1, 256>>>(pre_g, pre_b, 8, 0);

    // layer 1 (SIMT)
    gemm1_k<<<N_PTS/128, 128>>>(W1);
    zstat_k<<<1, 512>>>();
    stats_k<<<2048, 256>>>((const float*)py1, 64);
    bnparam_k<<<1, 256>>>(g1, b1, 64, 1);

    // layer 2: 64 -> 128
    mm_k<64,128,false><<<dim3(N_PTS/128, 1), 256>>>(
        (const float*)py1, (const float*)pwt2, (float*)py2, nullptr, 1);
    zstat_k<<<1, 512>>>();
    stats_k<<<2048, 256>>>((const float*)py2, 128);
    bnparam_k<<<1, 256>>>(g2, b2, 128, 2);

    // layer 3: 128 -> 256
    mm_k<128,256,false><<<dim3(N_PTS/128, 2), 256>>>(
        (const float*)py2, (const float*)pwt3, (float*)py3, nullptr, 2);
    zstat_k<<<1, 512>>>();
    stats_k<<<2048, 256>>>((const float*)py3, 256);
    bnparam_k<<<1, 256>>>(g3, b3, 256, 3);

    // layer 4: 256 -> 256 (+b4) -> y4
    mm_k<256,256,true><<<dim3(N_PTS/128, 2), 256>>>(
        (const float*)py3, (const float*)pwt4, (float*)py4, b4, 3);

    // voxel compress (CSR gather-max + 256->64 mma)
    comp_k<<<SS/128, 256>>>(bc);

    // residual output
    const int TOT = BB*192*HH*WW;
    residual_k<<<(TOT + 255)/256, 256>>>(out);

    (void)in_sizes; (void)n_in; (void)out_size;
}

// round 5
// speedup vs baseline: 1.9807x; 1.0009x over previous
#include <cuda_runtime.h>
#include <cstdint>
#include <cstddef>

// ---------------- problem constants ----------------
#define N_PTS 524288
#define BB 2
#define FF 4
#define HH 64
#define WW 512
#define SS (BB*FF*HH*WW)        // 262144 voxels
#define EPSBN 1e-5f

// ---------------- static device scratch ----------------
__device__ int   g_cnt[SS];
__device__ int   g_off[SS];
__device__ int   g_cursor[SS];
__device__ int   g_bsum[256];
__device__ int   g_boff[256];
__device__ int   g_csr[N_PTS];
__device__ float g_vsum[SS*3];
__device__ int   g_lin[N_PTS];
__device__ float g_feats[(size_t)N_PTS*8];
__device__ float g_y1[(size_t)N_PTS*64];
__device__ float g_y2[(size_t)N_PTS*128];
__device__ float g_y3[(size_t)N_PTS*256];
__device__ float g_y4[(size_t)N_PTS*256];
__device__ float g_comp[(size_t)SS*64];
__device__ float g_stat[512];          // [0:256) sum, [256:512) sumsq
__device__ float g_scale[4*256];
__device__ float g_shift[4*256];
__device__ float g_wt2[128*64];        // W2^T [n][k] tf32-rounded
__device__ float g_wt3[256*128];
__device__ float g_wt4[256*256];
__device__ float g_wtc[64*256];

// ---------------- helpers ----------------
__device__ __forceinline__ float tf32r(float x){
    uint32_t o;
    asm("cvt.rna.tf32.f32 %0, %1;" : "=r"(o) : "r"(__float_as_uint(x)));
    return __uint_as_float(o);
}
__device__ __forceinline__ void mma8(float* c, const uint32_t* a, uint32_t b0, uint32_t b1){
    asm volatile(
        "mma.sync.aligned.m16n8k8.row.col.f32.tf32.tf32.f32 "
        "{%0,%1,%2,%3}, {%4,%5,%6,%7}, {%8,%9}, {%0,%1,%2,%3};"
        : "+f"(c[0]), "+f"(c[1]), "+f"(c[2]), "+f"(c[3])
        : "r"(a[0]), "r"(a[1]), "r"(a[2]), "r"(a[3]), "r"(b0), "r"(b1));
}

// ---------------- small kernels ----------------
__global__ void init_k(){
    long stride = (long)gridDim.x * blockDim.x;
    for (long i = (long)blockIdx.x*blockDim.x + threadIdx.x; i < (long)SS*3; i += stride){
        g_vsum[i] = 0.0f;
        if (i < SS) g_cnt[i] = 0;
    }
}
__global__ void zstat_k(){ g_stat[threadIdx.x] = 0.0f; }

__global__ __launch_bounds__(256) void scatter_k(const float* __restrict__ pts,
                                                 const int* __restrict__ coors){
    int i = blockIdx.x*blockDim.x + threadIdx.x;
    if (i >= N_PTS) return;
    int c0 = coors[4*i+0], c1 = coors[4*i+1], c2 = coors[4*i+2], c3 = coors[4*i+3];
    int l = ((c0*FF + c1)*HH + c2)*WW + c3;
    g_lin[i] = l;
    float4 p = *(const float4*)&pts[4*i];
    atomicAdd(&g_cnt[l], 1);
    atomicAdd(&g_vsum[3*l+0], p.x);
    atomicAdd(&g_vsum[3*l+1], p.y);
    atomicAdd(&g_vsum[3*l+2], p.z);
}

// prefix scan of counts -> CSR offsets
__global__ __launch_bounds__(1024) void scan1_k(){
    __shared__ int s[1024];
    int t = threadIdx.x, g = blockIdx.x*1024 + t;
    int v = g_cnt[g]; s[t] = v; __syncthreads();
    #pragma unroll
    for (int d = 1; d < 1024; d <<= 1){
        int x = (t >= d) ? s[t-d] : 0; __syncthreads();
        s[t] += x; __syncthreads();
    }
    g_off[g] = s[t] - v;
    if (t == 1023) g_bsum[blockIdx.x] = s[t];
}
__global__ void scan2_k(){
    __shared__ int s[256];
    int t = threadIdx.x;
    int v = g_bsum[t]; s[t] = v; __syncthreads();
    #pragma unroll
    for (int d = 1; d < 256; d <<= 1){
        int x = (t >= d) ? s[t-d] : 0; __syncthreads();
        s[t] += x; __syncthreads();
    }
    g_boff[t] = s[t] - v;
}
__global__ __launch_bounds__(1024) void scan3_k(){
    int g = blockIdx.x*1024 + threadIdx.x;
    int o = g_off[g] + g_boff[blockIdx.x];
    g_off[g] = o; g_cursor[g] = o;
}
__global__ __launch_bounds__(256) void csrfill_k(){
    int i = blockIdx.x*256 + threadIdx.x;
    int l = g_lin[i];
    int slot = atomicAdd(&g_cursor[l], 1);
    g_csr[slot] = i;
}

// feats (N x 8) + block-reduced channel stats
__global__ __launch_bounds__(256) void feats_k(const float* __restrict__ pts){
    __shared__ float st[16];
    int tid = threadIdx.x;
    if (tid < 16) st[tid] = 0.0f;
    __syncthreads();
    int i = blockIdx.x*blockDim.x + tid;
    float4 p = *(const float4*)&pts[4*i];
    int l = g_lin[i];
    float inv = 1.0f / fmaxf((float)g_cnt[l], 1.0f);
    float mx = g_vsum[3*l+0]*inv, my = g_vsum[3*l+1]*inv, mz = g_vsum[3*l+2]*inv;
    float f[8];
    f[0]=p.x; f[1]=p.y; f[2]=p.z; f[3]=p.w;
    f[4]=sqrtf(p.x*p.x + p.y*p.y + p.z*p.z);
    f[5]=p.x-mx; f[6]=p.y-my; f[7]=p.z-mz;
    *(float4*)&g_feats[(size_t)i*8]   = make_float4(f[0],f[1],f[2],f[3]);
    *(float4*)&g_feats[(size_t)i*8+4] = make_float4(f[4],f[5],f[6],f[7]);
    #pragma unroll
    for (int ch = 0; ch < 8; ch++){
        float s = f[ch], q = f[ch]*f[ch];
        #pragma unroll
        for (int o = 16; o; o >>= 1){
            s += __shfl_xor_sync(0xFFFFFFFFu, s, o);
            q += __shfl_xor_sync(0xFFFFFFFFu, q, o);
        }
        if ((tid & 31) == 0){
            atomicAdd(&st[ch], s);
            atomicAdd(&st[8+ch], q);
        }
    }
    __syncthreads();
    if (tid < 8)              atomicAdd(&g_stat[tid], st[tid]);
    else if (tid < 16)        atomicAdd(&g_stat[256 + tid - 8], st[tid]);
}

__global__ void bnparam_k(const float* __restrict__ gam, const float* __restrict__ bet,
                          int C, int layer){
    int c = threadIdx.x;
    if (c < C){
        float n = (float)N_PTS;
        float m = g_stat[c] / n;
        float v = g_stat[256+c] / n - m*m;
        float sc = gam[c] / sqrtf(v + EPSBN);
        g_scale[layer*256+c] = sc;
        g_shift[layer*256+c] = bet[c] - m*sc;
    }
}

__global__ __launch_bounds__(256) void stats_k(const float* __restrict__ y, int C){
    int tid = threadIdx.x;
    int rpb = 256 / C;
    int c  = tid % C;
    int rr = tid / C;
    float s = 0.0f, q = 0.0f;
    for (long row = (long)blockIdx.x*rpb + rr; row < N_PTS; row += (long)gridDim.x*rpb){
        float v = y[row*(long)C + c];
        s += v; q += v*v;
    }
    __shared__ float sm[256];
    sm[tid] = s; __syncthreads();
    if (tid < C){
        float t = 0.0f;
        for (int j = 0; j < rpb; j++) t += sm[tid + j*C];
        atomicAdd(&g_stat[tid], t);
    }
    __syncthreads();
    sm[tid] = q; __syncthreads();
    if (tid < C){
        float t = 0.0f;
        for (int j = 0; j < rpb; j++) t += sm[tid + j*C];
        atomicAdd(&g_stat[256+tid], t);
    }
}

// layer 1: feats(8) -> y1(64), BN0 affine on load (SIMT)
__global__ __launch_bounds__(128) void gemm1_k(const float* __restrict__ W1){
    __shared__ float Ws[8][64];
    __shared__ float sc[8], sh[8];
    int tid = threadIdx.x;
    for (int i = tid; i < 512; i += 128) Ws[i>>6][i&63] = W1[i];
    if (tid < 8){ sc[tid] = g_scale[tid]; sh[tid] = g_shift[tid]; }
    __syncthreads();
    int row = blockIdx.x*128 + tid;
    float4 fa = *(const float4*)&g_feats[(size_t)row*8];
    float4 fb = *(const float4*)&g_feats[(size_t)row*8+4];
    float f[8] = {fa.x,fa.y,fa.z,fa.w,fb.x,fb.y,fb.z,fb.w};
    #pragma unroll
    for (int k = 0; k < 8; k++) f[k] = f[k]*sc[k] + sh[k];
    #pragma unroll
    for (int c4 = 0; c4 < 16; c4++){
        float4 acc = make_float4(0,0,0,0);
        #pragma unroll
        for (int k = 0; k < 8; k++){
            float4 w = *(const float4*)&Ws[k][c4*4];
            acc.x += f[k]*w.x; acc.y += f[k]*w.y;
            acc.z += f[k]*w.z; acc.w += f[k]*w.w;
        }
        *(float4*)&g_y1[(size_t)row*64 + c4*4] = acc;
    }
}

// transpose W [K][C] -> Wt [C][K], tf32-round
__global__ __launch_bounds__(256) void tr_k(const float* __restrict__ W,
                                            float* __restrict__ Wt, int Kd, int Cd){
    int i = blockIdx.x*256 + threadIdx.x;
    if (i >= Kd*Cd) return;
    int n = i / Kd, k = i % Kd;
    Wt[i] = tf32r(W[k*Cd + n]);
}

// ---------------- mma.sync tf32 GEMM ----------------
// Y[N x COUT] = relu(A*scale+shift) @ Bt^T + (bias)
// A row-major [N][K] fp32, Bt [COUT][K] tf32-rounded.
// Block tile 128x128, BK=32, 8 warps (4 m x 2 n), warp tile 32x64.
template<int K, int COUT, bool ADD_BIAS>
__global__ __launch_bounds__(256) void mm_k(const float* __restrict__ A,
                                            const float* __restrict__ Bt,
                                            float* __restrict__ Y,
                                            const float* __restrict__ bias,
                                            int layer){
    __shared__ float As[128][36];
    __shared__ float Bs[128][36];
    constexpr int NIT = K/32;

    int tid = threadIdx.x, wid = tid >> 5, lane = tid & 31;
    int row0 = blockIdx.x*128, col0 = blockIdx.y*128;
    int m_base = (wid & 3)*32, n_base = (wid >> 2)*64;
    int gr = lane >> 2, q = lane & 3;

    int lr = tid >> 1;                 // 0..127 (row / n)
    int lk = (tid & 1)*16;             // k-offset within BK (float units)

    float acc[2][8][4];
    #pragma unroll
    for (int i = 0; i < 2; i++)
        #pragma unroll
        for (int j = 0; j < 8; j++)
            #pragma unroll
            for (int c = 0; c < 4; c++) acc[i][j][c] = 0.0f;

    const float* scp = &g_scale[layer*256];
    const float* shp = &g_shift[layer*256];

    float4 ar[4], br[4];
    // prefetch iter 0
    {
        const float* Ap = &A[(size_t)(row0 + lr)*K + lk];
        const float* Bp = &Bt[(size_t)(col0 + lr)*K + lk];
        #pragma unroll
        for (int j = 0; j < 4; j++){ ar[j] = *(const float4*)&Ap[j*4]; br[j] = *(const float4*)&Bp[j*4]; }
    }
    // transform + store iter 0
    #pragma unroll
    for (int j = 0; j < 4; j++){
        float4 sc4 = *(const float4*)&scp[lk + j*4];
        float4 sh4 = *(const float4*)&shp[lk + j*4];
        float4 v = ar[j];
        v.x = tf32r(fmaxf(v.x*sc4.x + sh4.x, 0.0f));
        v.y = tf32r(fmaxf(v.y*sc4.y + sh4.y, 0.0f));
        v.z = tf32r(fmaxf(v.z*sc4.z + sh4.z, 0.0f));
        v.w = tf32r(fmaxf(v.w*sc4.w + sh4.w, 0.0f));
        *(float4*)&As[lr][lk + j*4] = v;
        *(float4*)&Bs[lr][lk + j*4] = br[j];
    }
    __syncthreads();

    for (int it = 0; it < NIT; it++){
        int k0n = (it+1)*32;
        if (it+1 < NIT){
            const float* Ap = &A[(size_t)(row0 + lr)*K + k0n + lk];
            const float* Bp = &Bt[(size_t)(col0 + lr)*K + k0n + lk];
            #pragma unroll
            for (int j = 0; j < 4; j++){ ar[j] = *(const float4*)&Ap[j*4]; br[j] = *(const float4*)&Bp[j*4]; }
        }
        #pragma unroll
        for (int kk = 0; kk < 4; kk++){
            int k = kk*8;
            uint32_t a[2][4];
            #pragma unroll
            for (int i = 0; i < 2; i++){
                int m = m_base + i*16 + gr;
                a[i][0] = __float_as_uint(As[m][k + q]);
                a[i][1] = __float_as_uint(As[m+8][k + q]);
                a[i][2] = __float_as_uint(As[m][k + 4 + q]);
                a[i][3] = __float_as_uint(As[m+8][k + 4 + q]);
            }
            #pragma unroll
            for (int j = 0; j < 8; j++){
                int n = n_base + j*8 + gr;
                uint32_t b0 = __float_as_uint(Bs[n][k + q]);
                uint32_t b1 = __float_as_uint(Bs[n][k + 4 + q]);
                mma8(acc[0][j], a[0], b0, b1);
                mma8(acc[1][j], a[1], b0, b1);
            }
        }
        if (it+1 < NIT){
            __syncthreads();
            #pragma unroll
            for (int j = 0; j < 4; j++){
                float4 sc4 = *(const float4*)&scp[k0n + lk + j*4];
                float4 sh4 = *(const float4*)&shp[k0n + lk + j*4];
                float4 v = ar[j];
                v.x = tf32r(fmaxf(v.x*sc4.x + sh4.x, 0.0f));
                v.y = tf32r(fmaxf(v.y*sc4.y + sh4.y, 0.0f));
                v.z = tf32r(fmaxf(v.z*sc4.z + sh4.z, 0.0f));
                v.w = tf32r(fmaxf(v.w*sc4.w + sh4.w, 0.0f));
                *(float4*)&As[lr][lk + j*4] = v;
                *(float4*)&Bs[lr][lk + j*4] = br[j];
            }
            __syncthreads();
        }
    }

    // epilogue: direct stores (float2 per fragment pair)
    #pragma unroll
    for (int i = 0; i < 2; i++){
        #pragma unroll
        for (int j = 0; j < 8; j++){
            int col = col0 + n_base + j*8 + 2*q;
            int r0 = row0 + m_base + i*16 + gr;
            float2 lo = make_float2(acc[i][j][0], acc[i][j][1]);
            float2 hi = make_float2(acc[i][j][2], acc[i][j][3]);
            if (ADD_BIAS){
                float bx = bias[col], by = bias[col+1];
                lo.x += bx; lo.y += by; hi.x += bx; hi.y += by;
            }
            *(float2*)&Y[(size_t)r0*COUT + col]     = lo;
            *(float2*)&Y[(size_t)(r0+8)*COUT + col] = hi;
        }
    }
}

// ---------------- voxel compress: CSR gather-max + tf32 mma 256->64 ----------------
// Block tile 128(vox) x 64, BK=32, 8 warps (4 m x 2 n), warp tile 32x32.
__global__ __launch_bounds__(256) void comp_k(const float* __restrict__ bc){
    __shared__ float As[128][36];
    __shared__ float Bs[64][36];
    __shared__ int scnt[128], soff[128];

    int tid = threadIdx.x, wid = tid >> 5, lane = tid & 31;
    int row0 = blockIdx.x*128;
    int m_base = (wid & 3)*32, n_base = (wid >> 2)*32;
    int gr = lane >> 2, q = lane & 3;

    if (tid < 128){ scnt[tid] = g_cnt[row0+tid]; soff[tid] = g_off[row0+tid]; }
    __syncthreads();

    float acc[2][4][4];
    #pragma unroll
    for (int i = 0; i < 2; i++)
        #pragma unroll
        for (int j = 0; j < 4; j++)
            #pragma unroll
            for (int c = 0; c < 4; c++) acc[i][j][c] = 0.0f;

    int v = tid >> 1, half = tid & 1;
    int cnt = scnt[v], off0 = soff[v];

    for (int it = 0; it < 8; it++){
        int k0 = it*32;
        // B: 64 x 32 from g_wtc
        #pragma unroll
        for (int i = 0; i < 2; i++){
            int idx = i*256 + tid;
            int n = idx >> 3, kq = idx & 7;
            *(float4*)&Bs[n][kq*4] = *(const float4*)&g_wtc[n*256 + k0 + kq*4];
        }
        // A: gather-max 16 cols per thread
        {
            int kbase = k0 + half*16;
            float4 m4[4];
            if (cnt == 0){
                #pragma unroll
                for (int t = 0; t < 4; t++) m4[t] = make_float4(0,0,0,0);
            } else {
                const float* src = &g_y4[(size_t)g_csr[off0]*256 + kbase];
                #pragma unroll
                for (int t = 0; t < 4; t++) m4[t] = *(const float4*)&src[t*4];
                for (int jj = 1; jj < cnt; jj++){
                    const float* sj = &g_y4[(size_t)g_csr[off0+jj]*256 + kbase];
                    #pragma unroll
                    for (int t = 0; t < 4; t++){
                        float4 w = *(const float4*)&sj[t*4];
                        m4[t].x = fmaxf(m4[t].x, w.x); m4[t].y = fmaxf(m4[t].y, w.y);
                        m4[t].z = fmaxf(m4[t].z, w.z); m4[t].w = fmaxf(m4[t].w, w.w);
                    }
                }
            }
            #pragma unroll
            for (int t = 0; t < 4; t++){
                m4[t].x = tf32r(m4[t].x); m4[t].y = tf32r(m4[t].y);
                m4[t].z = tf32r(m4[t].z); m4[t].w = tf32r(m4[t].w);
                *(float4*)&As[v][half*16 + t*4] = m4[t];
            }
        }
        __syncthreads();
        #pragma unroll
        for (int kk = 0; kk < 4; kk++){
            int k = kk*8;
            uint32_t a[2][4];
            #pragma unroll
            for (int i = 0; i < 2; i++){
                int m = m_base + i*16 + gr;
                a[i][0] = __float_as_uint(As[m][k + q]);
                a[i][1] = __float_as_uint(As[m+8][k + q]);
                a[i][2] = __float_as_uint(As[m][k + 4 + q]);
                a[i][3] = __float_as_uint(As[m+8][k + 4 + q]);
            }
            #pragma unroll
            for (int j = 0; j < 4; j++){
                int n = n_base + j*8 + gr;
                uint32_t b0 = __float_as_uint(Bs[n][k + q]);
                uint32_t b1 = __float_as_uint(Bs[n][k + 4 + q]);
                mma8(acc[0][j], a[0], b0, b1);
                mma8(acc[1][j], a[1], b0, b1);
            }
        }
        __syncthreads();
    }

    #pragma unroll
    for (int i = 0; i < 2; i++){
        #pragma unroll
        for (int j = 0; j < 4; j++){
            int col = n_base + j*8 + 2*q;
            int r0 = m_base + i*16 + gr;
            float m0 = (scnt[r0]   > 0) ? 1.0f : 0.0f;
            float m1 = (scnt[r0+8] > 0) ? 1.0f : 0.0f;
            float bx = bc[col], by = bc[col+1];
            float2 lo, hi;
            lo.x = fmaxf(acc[i][j][0] + bx, 0.0f)*m0;
            lo.y = fmaxf(acc[i][j][1] + by, 0.0f)*m0;
            hi.x = fmaxf(acc[i][j][2] + bx, 0.0f)*m1;
            hi.y = fmaxf(acc[i][j][3] + by, 0.0f)*m1;
            *(float2*)&g_comp[(size_t)(row0 + r0)*64 + col]     = lo;
            *(float2*)&g_comp[(size_t)(row0 + r0 + 8)*64 + col] = hi;
        }
    }
}

// ---------------- residual assembly: out (B, 192, H, W) ----------------
__global__ __launch_bounds__(256) void residual_k(float* __restrict__ out){
    int idx = blockIdx.x*blockDim.x + threadIdx.x;
    const int TOT = BB*192*HH*WW;
    if (idx >= TOT) return;
    int w  = idx % WW;
    int h  = (idx / WW) % HH;
    int ch = (idx / (WW*HH)) % 192;
    int b  = idx / (WW*HH*192);
    int f = ch >> 6, j = ch & 63;
    int vl = ((b*FF + (FF-1))*HH + h)*WW + w;
    int vf = ((b*FF + f)*HH + h)*WW + w;
    out[idx] = g_comp[(size_t)vl*64 + j] - g_comp[(size_t)vf*64 + j];
}

// ---------------- host launcher ----------------
extern "C" void kernel_launch(void* const* d_in, const int* in_sizes, int n_in,
                              void* d_out, int out_size){
    const float* pts   = (const float*)d_in[0];
    const int*   coors = (const int*)  d_in[1];
    const float* pre_g = (const float*)d_in[2];
    const float* pre_b = (const float*)d_in[3];
    const float* W1    = (const float*)d_in[4];
    const float* g1    = (const float*)d_in[5];
    const float* b1    = (const float*)d_in[6];
    const float* W2    = (const float*)d_in[7];
    const float* g2    = (const float*)d_in[8];
    const float* b2    = (const float*)d_in[9];
    const float* W3    = (const float*)d_in[10];
    const float* g3    = (const float*)d_in[11];
    const float* b3    = (const float*)d_in[12];
    const float* W4    = (const float*)d_in[13];
    const float* b4    = (const float*)d_in[14];
    const float* Wc    = (const float*)d_in[15];
    const float* bc    = (const float*)d_in[16];
    float* out = (float*)d_out;

    void *py1, *py2, *py3, *py4, *pwt2, *pwt3, *pwt4, *pwtc;
    cudaGetSymbolAddress(&py1, g_y1);
    cudaGetSymbolAddress(&py2, g_y2);
    cudaGetSymbolAddress(&py3, g_y3);
    cudaGetSymbolAddress(&py4, g_y4);
    cudaGetSymbolAddress(&pwt2, g_wt2);
    cudaGetSymbolAddress(&pwt3, g_wt3);
    cudaGetSymbolAddress(&pwt4, g_wt4);
    cudaGetSymbolAddress(&pwtc, g_wtc);

    // init + weight transposes
    init_k<<<1024, 256>>>();
    zstat_k<<<1, 512>>>();
    tr_k<<<(128*64 + 255)/256, 256>>>(W2, (float*)pwt2, 64, 128);
    tr_k<<<(256*128 + 255)/256, 256>>>(W3, (float*)pwt3, 128, 256);
    tr_k<<<(256*256 + 255)/256, 256>>>(W4, (float*)pwt4, 256, 256);
    tr_k<<<(64*256 + 255)/256, 256>>>(Wc, (float*)pwtc, 256, 64);

    // voxel scatter + CSR build
    scatter_k<<<N_PTS/256, 256>>>(pts, coors);
    scan1_k<<<SS/1024, 1024>>>();
    scan2_k<<<1, 256>>>();
    scan3_k<<<SS/1024, 1024>>>();
    csrfill_k<<<N_PTS/256, 256>>>();

    // feats + pre-norm
    feats_k<<<N_PTS/256, 256>>>(pts);
    bnparam_k<<<1, 256>>>(pre_g, pre_b, 8, 0);

    // layer 1 (SIMT)
    gemm1_k<<<N_PTS/128, 128>>>(W1);
    zstat_k<<<1, 512>>>();
    stats_k<<<2048, 256>>>((const float*)py1, 64);
    bnparam_k<<<1, 256>>>(g1, b1, 64, 1);

    // layer 2: 64 -> 128
    mm_k<64,128,false><<<dim3(N_PTS/128, 1), 256>>>(
        (const float*)py1, (const float*)pwt2, (float*)py2, nullptr, 1);
    zstat_k<<<1, 512>>>();
    stats_k<<<2048, 256>>>((const float*)py2, 128);
    bnparam_k<<<1, 256>>>(g2, b2, 128, 2);

    // layer 3: 128 -> 256
    mm_k<128,256,false><<<dim3(N_PTS/128, 2), 256>>>(
        (const float*)py2, (const float*)pwt3, (float*)py3, nullptr, 2);
    zstat_k<<<1, 512>>>();
    stats_k<<<2048, 256>>>((const float*)py3, 256);
    bnparam_k<<<1, 256>>>(g3, b3, 256, 3);

    // layer 4: 256 -> 256 (+b4) -> y4
    mm_k<256,256,true><<<dim3(N_PTS/128, 2), 256>>>(
        (const float*)py3, (const float*)pwt4, (float*)py4, b4, 3);

    // voxel compress (CSR gather-max + 256->64 mma)
    comp_k<<<SS/128, 256>>>(bc);

    // residual output
    const int TOT = BB*192*HH*WW;
    residual_k<<<(TOT + 255)/256, 256>>>(out);

    (void)in_sizes; (void)n_in; (void)out_size;
}